// round 5
// baseline (speedup 1.0000x reference)
#include <cuda_runtime.h>
#include <cstdint>

#define N_GENOMES 30000
#define N_GENES   240000
#define N_SAMPLES 128
#define N_SEQS    80000
#define CAP       32   // Poisson(3): P(any of 80K seqs > 32 genes) ~ 1e-16

// Scratch (device globals: no allocation allowed).
// pairs payload: {row element offset = genome_idx*128, bits(pos)}.
// Unwritten slots are zero-initialized (module load) or hold prior
// deterministic values -> always a valid in-range offset; masked in compute.
__device__ int  d_count[N_SEQS];
__device__ int2 d_pairs[(size_t)N_SEQS * CAP];

__global__ void __launch_bounds__(256) scatter_kernel(
    const int*   __restrict__ seq_idx,
    const int*   __restrict__ genome_idx,
    const float* __restrict__ pos)
{
    int g = blockIdx.x * blockDim.x + threadIdx.x;
    if (g >= N_GENES) return;
    int s    = seq_idx[g];
    int off  = genome_idx[g] * N_SAMPLES;   // precomputed row offset
    float p  = pos[g];
    int slot = atomicAdd(&d_count[s], 1);
    if (slot < CAP)
        d_pairs[(size_t)s * CAP + slot] = make_int2(off, __float_as_int(p));
}

// One warp per seq. Lane-parallel bucket fetch, shfl broadcast, 4-deep
// branchless unroll (8 gathers in flight), mask folded into accumulate FMA.
__global__ void __launch_bounds__(64) seq_segsum_kernel(
    const float* __restrict__ A,
    const float* __restrict__ B,
    float*       __restrict__ out)
{
    const int seq  = blockIdx.x * 2 + (threadIdx.x >> 5);
    const int lane = threadIdx.x & 31;
    if (seq >= N_SEQS) return;

    // Both metadata loads issue immediately (independent).
    const int  t  = min(__ldg(&d_count[seq]), CAP);
    const int2 pr = d_pairs[(size_t)seq * CAP + lane];

    const int col = lane * 4;
    float4 acc = make_float4(0.f, 0.f, 0.f, 0.f);

    for (int k = 0; k < t; k += 4) {
        int   off[4];
        float pp[4], m[4];
        #pragma unroll
        for (int u = 0; u < 4; u++) {
            // shfl src may exceed 31 on the last iter; wraps to a valid lane's
            // offset -> in-range read, contribution masked by m[u]=0.
            off[u] = __shfl_sync(0xffffffffu, pr.x, k + u) + col;
            pp[u]  = __int_as_float(__shfl_sync(0xffffffffu, pr.y, k + u));
            m[u]   = ((k + u) < t) ? 1.0f : 0.0f;
        }
        #pragma unroll
        for (int u = 0; u < 4; u++) {
            const float4 a = *reinterpret_cast<const float4*>(A + off[u]);
            const float4 b = *reinterpret_cast<const float4*>(B + off[u]);
            float4 e;
            e.x = __expf(fmaf(-pp[u], b.x, a.x) + 1.0f);
            e.y = __expf(fmaf(-pp[u], b.y, a.y) + 1.0f);
            e.z = __expf(fmaf(-pp[u], b.z, a.z) + 1.0f);
            e.w = __expf(fmaf(-pp[u], b.w, a.w) + 1.0f);
            acc.x = fmaf(e.x, m[u], acc.x);
            acc.y = fmaf(e.y, m[u], acc.y);
            acc.z = fmaf(e.z, m[u], acc.z);
            acc.w = fmaf(e.w, m[u], acc.w);
        }
    }

    *reinterpret_cast<float4*>(out + (size_t)seq * N_SAMPLES + col) = acc;
}

extern "C" void kernel_launch(void* const* d_in, const int* in_sizes, int n_in,
                              void* d_out, int out_size)
{
    const float* A          = (const float*)d_in[0];
    const float* B          = (const float*)d_in[1];
    const float* pos        = (const float*)d_in[2];
    const int*   genome_idx = (const int*)d_in[3];
    const int*   seq_idx    = (const int*)d_in[4];
    float*       out        = (float*)d_out;

    void* count_ptr = nullptr;
    cudaGetSymbolAddress(&count_ptr, d_count);
    cudaMemsetAsync(count_ptr, 0, sizeof(int) * N_SEQS, 0);

    scatter_kernel<<<(N_GENES + 255) / 256, 256>>>(seq_idx, genome_idx, pos);

    // 2 warps (2 seqs) per 64-thread block.
    seq_segsum_kernel<<<(N_SEQS + 1) / 2, 64>>>(A, B, out);
}

// round 6
// speedup vs baseline: 1.0814x; 1.0814x over previous
#include <cuda_runtime.h>
#include <cstdint>

#define N_GENOMES 30000
#define N_GENES   240000
#define N_SAMPLES 128
#define N_SEQS    80000
#define CAP       32   // Poisson(3): P(any of 80K seqs > 32 genes) ~ 1e-16

// Scratch (device globals: no allocation allowed).
// pairs payload: {row element offset = genome_idx*128, bits(pos)}.
__device__ int  d_count[N_SEQS];
__device__ int2 d_pairs[(size_t)N_SEQS * CAP];

__global__ void __launch_bounds__(256) scatter_kernel(
    const int*   __restrict__ seq_idx,
    const int*   __restrict__ genome_idx,
    const float* __restrict__ pos)
{
    int g = blockIdx.x * blockDim.x + threadIdx.x;
    if (g >= N_GENES) return;
    int s    = seq_idx[g];
    int off  = genome_idx[g] * N_SAMPLES;
    float p  = pos[g];
    int slot = atomicAdd(&d_count[s], 1);
    if (slot < CAP)
        d_pairs[(size_t)s * CAP + slot] = make_int2(off, __float_as_int(p));
}

// Persistent grid-stride warps: one warp owns ~17 seqs. Metadata for the NEXT
// seq is prefetched before computing the current one, hiding the L2 latency
// that previously headed every short-lived warp. Branchless 4-deep unroll,
// mask folded into the accumulate FMA (8 LDG.128 in flight per step).
__global__ void __launch_bounds__(256) seq_segsum_kernel(
    const float* __restrict__ A,
    const float* __restrict__ B,
    float*       __restrict__ out)
{
    const int lane   = threadIdx.x & 31;
    const int stride = (gridDim.x * blockDim.x) >> 5;
    int seq = (blockIdx.x * blockDim.x + threadIdx.x) >> 5;
    if (seq >= N_SEQS) return;

    const int col = lane * 4;

    // Prime the metadata pipeline.
    int  tn  = __ldg(&d_count[seq]);
    int2 prn = d_pairs[(size_t)seq * CAP + lane];

    while (true) {
        const int  t  = min(tn, CAP);
        const int2 pr = prn;

        const int nseq = seq + stride;
        if (nseq < N_SEQS) {           // prefetch next seq's metadata now
            tn  = __ldg(&d_count[nseq]);
            prn = d_pairs[(size_t)nseq * CAP + lane];
        }

        float4 acc = make_float4(0.f, 0.f, 0.f, 0.f);
        for (int k = 0; k < t; k += 4) {
            int   off[4];
            float pp[4], m[4];
            #pragma unroll
            for (int u = 0; u < 4; u++) {
                // Out-of-range shfl src wraps to a valid lane -> in-range
                // offset; contribution masked by m[u]=0.
                off[u] = __shfl_sync(0xffffffffu, pr.x, k + u) + col;
                pp[u]  = __int_as_float(__shfl_sync(0xffffffffu, pr.y, k + u));
                m[u]   = ((k + u) < t) ? 1.0f : 0.0f;
            }
            #pragma unroll
            for (int u = 0; u < 4; u++) {
                const float4 a = *reinterpret_cast<const float4*>(A + off[u]);
                const float4 b = *reinterpret_cast<const float4*>(B + off[u]);
                float4 e;
                e.x = __expf(fmaf(-pp[u], b.x, a.x) + 1.0f);
                e.y = __expf(fmaf(-pp[u], b.y, a.y) + 1.0f);
                e.z = __expf(fmaf(-pp[u], b.z, a.z) + 1.0f);
                e.w = __expf(fmaf(-pp[u], b.w, a.w) + 1.0f);
                acc.x = fmaf(e.x, m[u], acc.x);
                acc.y = fmaf(e.y, m[u], acc.y);
                acc.z = fmaf(e.z, m[u], acc.z);
                acc.w = fmaf(e.w, m[u], acc.w);
            }
        }

        *reinterpret_cast<float4*>(out + (size_t)seq * N_SAMPLES + col) = acc;

        if (nseq >= N_SEQS) break;
        seq = nseq;
    }
}

extern "C" void kernel_launch(void* const* d_in, const int* in_sizes, int n_in,
                              void* d_out, int out_size)
{
    const float* A          = (const float*)d_in[0];
    const float* B          = (const float*)d_in[1];
    const float* pos        = (const float*)d_in[2];
    const int*   genome_idx = (const int*)d_in[3];
    const int*   seq_idx    = (const int*)d_in[4];
    float*       out        = (float*)d_out;

    void* count_ptr = nullptr;
    cudaGetSymbolAddress(&count_ptr, d_count);
    cudaMemsetAsync(count_ptr, 0, sizeof(int) * N_SEQS, 0);

    scatter_kernel<<<(N_GENES + 255) / 256, 256>>>(seq_idx, genome_idx, pos);

    // One persistent wave: 152 SMs x 4 blocks x 8 warps ~= 4864 warps.
    seq_segsum_kernel<<<608, 256>>>(A, B, out);
}

// round 7
// speedup vs baseline: 1.1349x; 1.0495x over previous
#include <cuda_runtime.h>
#include <cstdint>

#define N_GENOMES 30000
#define N_GENES   240000
#define N_SAMPLES 128
#define N_SEQS    80000
#define CAP       32   // Poisson(3): P(any of 80K seqs > 32 genes) ~ 1e-16
#define LOG2E     1.4426950408889634f

// Scratch (device globals, zero-initialized at module load).
// pairs payload: {row element offset = genome_idx*128, bits(-pos*log2e)}.
__device__ int  d_count[N_SEQS];
__device__ int2 d_pairs[(size_t)N_SEQS * CAP];

__global__ void __launch_bounds__(256) scatter_kernel(
    const int*   __restrict__ seq_idx,
    const int*   __restrict__ genome_idx,
    const float* __restrict__ pos)
{
    int g = blockIdx.x * blockDim.x + threadIdx.x;
    if (g >= N_GENES) return;
    int   s   = seq_idx[g];
    int   off = genome_idx[g] * N_SAMPLES;
    float pn  = -pos[g] * LOG2E;               // fold log2e at scatter time
    int slot = atomicAdd(&d_count[s], 1);
    if (slot < CAP)
        d_pairs[(size_t)s * CAP + slot] = make_int2(off, __float_as_int(pn));
}

__device__ __forceinline__ float ex2f(float x) {
    float r; asm("ex2.approx.f32 %0, %1;" : "=f"(r) : "f"(x)); return r;
}

// exp(A + 1 - p*B) = ex2( fma(B, -p*log2e, fma(A, log2e, log2e)) )
__device__ __forceinline__ void acc_gene(float4& acc, const float4 a,
                                         const float4 b, const float pn) {
    acc.x += ex2f(fmaf(b.x, pn, fmaf(a.x, LOG2E, LOG2E)));
    acc.y += ex2f(fmaf(b.y, pn, fmaf(a.y, LOG2E, LOG2E)));
    acc.z += ex2f(fmaf(b.z, pn, fmaf(a.z, LOG2E, LOG2E)));
    acc.w += ex2f(fmaf(b.w, pn, fmaf(a.w, LOG2E, LOG2E)));
}

// Persistent warps, one seq at a time. Next-seq metadata prefetched across
// iterations; within a seq, gene k+1's A/B rows are prefetched while gene k
// computes (software pipeline). Exact trip count: zero masked waste.
// Resets d_count after reading so the next graph replay needs no memset.
__global__ void __launch_bounds__(256) seq_segsum_kernel(
    const float* __restrict__ A,
    const float* __restrict__ B,
    float*       __restrict__ out)
{
    const int lane   = threadIdx.x & 31;
    const int nwarps = (gridDim.x * blockDim.x) >> 5;
    int seq = (blockIdx.x * blockDim.x + threadIdx.x) >> 5;
    if (seq >= N_SEQS) return;
    const int col = lane * 4;

    // Prime the metadata pipeline.
    int  tn  = __ldg(&d_count[seq]);
    int2 prn = d_pairs[(size_t)seq * CAP + lane];

    while (true) {
        const int  t  = min(tn, CAP);
        const int2 pr = prn;
        if (lane == 0) d_count[seq] = 0;         // reset for next replay

        const int nseq = seq + nwarps;
        if (nseq < N_SEQS) {                     // prefetch next seq metadata
            tn  = __ldg(&d_count[nseq]);
            prn = d_pairs[(size_t)nseq * CAP + lane];
        }

        float4 acc = make_float4(0.f, 0.f, 0.f, 0.f);
        if (t > 0) {
            int   off = __shfl_sync(0xffffffffu, pr.x, 0) + col;
            float pn  = __int_as_float(__shfl_sync(0xffffffffu, pr.y, 0));
            float4 a = *reinterpret_cast<const float4*>(A + off);
            float4 b = *reinterpret_cast<const float4*>(B + off);

            for (int k = 1; k < t; k++) {
                const int   offn = __shfl_sync(0xffffffffu, pr.x, k) + col;
                const float pnn  = __int_as_float(__shfl_sync(0xffffffffu, pr.y, k));
                const float4 an = *reinterpret_cast<const float4*>(A + offn);
                const float4 bn = *reinterpret_cast<const float4*>(B + offn);
                acc_gene(acc, a, b, pn);         // compute k-1 while k loads fly
                a = an; b = bn; pn = pnn;
            }
            acc_gene(acc, a, b, pn);             // epilogue: last gene
        }

        *reinterpret_cast<float4*>(out + (size_t)seq * N_SAMPLES + col) = acc;

        if (nseq >= N_SEQS) break;
        seq = nseq;
    }
}

extern "C" void kernel_launch(void* const* d_in, const int* in_sizes, int n_in,
                              void* d_out, int out_size)
{
    const float* A          = (const float*)d_in[0];
    const float* B          = (const float*)d_in[1];
    const float* pos        = (const float*)d_in[2];
    const int*   genome_idx = (const int*)d_in[3];
    const int*   seq_idx    = (const int*)d_in[4];
    float*       out        = (float*)d_out;

    scatter_kernel<<<(N_GENES + 255) / 256, 256>>>(seq_idx, genome_idx, pos);

    // One persistent wave: ~4864 warps.
    seq_segsum_kernel<<<608, 256>>>(A, B, out);
}